// round 9
// baseline (speedup 1.0000x reference)
#include <cuda_runtime.h>
#include <cuda_bf16.h>
#include <math.h>
#include <stdint.h>

#define BB 8
#define LL 4096
#define DM 96
#define DI 192
#define DS 8
#define DR 6
#define NTOK (BB*LL)
#define CS 32
#define NC (LL/CS)
#define TCONV 32

// ---------------- scratch (device globals; no allocations) ----------------
__device__ float g_rs[NTOK];                 // per-token rsqrt(meansq+eps)
__device__ __nv_bfloat16 g_x[NTOK*DI];       // pre-conv x (bf16)
__device__ __nv_bfloat16 g_z[NTOK*DI];       // silu(z) (bf16)
__device__ __nv_bfloat162 g_dx[NTOK*DI];     // packed {delta, xc} bf16
__device__ float g_Bm[NTOK*DS];
__device__ float g_Cm[NTOK*DS];
__device__ float g_S[BB*DI*NC];              // per-chunk sum of delta
__device__ float g_hend[BB*DI*NC*DS];        // per-chunk local h end
__device__ float g_hinit[BB*DI*NC*DS];       // per-chunk initial h
__device__ float g_ysum[BB*DI];              // sum_t y_t*silu(z_t) per (b,d)
__device__ float g_usum[BB*DM];              // sum_t u per (b,k)

__device__ __forceinline__ float siluf(float v) { return v / (1.0f + __expf(-v)); }
__device__ __forceinline__ float ex2f(float x) { float y; asm("ex2.approx.f32 %0, %1;" : "=f"(y) : "f"(x)); return y; }
__device__ __forceinline__ float tf32r(float x) {
    unsigned u; asm("cvt.rna.tf32.f32 %0, %1;" : "=r"(u) : "f"(x)); return __uint_as_float(u);
}
#define LOG2E 1.4426950408889634f

// ---------------- kernel 0: zero accumulators ----------------
__global__ void k_zero() {
    int i = blockIdx.x * blockDim.x + threadIdx.x;
    if (i < BB*DM) g_usum[i] = 0.0f;
    if (i < BB*DI) g_ysum[i] = 0.0f;
}

// ---------------- kernel 1: per-row rsqrt + batch-mean (block-reduced) ----------------
__global__ void k_rs(const float* __restrict__ u) {
    __shared__ float su[DM];
    int tid = threadIdx.x;
    int warp = (blockIdx.x * blockDim.x + tid) >> 5;
    int lane = tid & 31;
    if (tid < DM) su[tid] = 0.0f;
    __syncthreads();
    int b = warp / LL;
    const float* up = u + (size_t)warp * DM;
    float a0 = up[lane], a1 = up[lane+32], a2 = up[lane+64];
    float ss = a0*a0 + a1*a1 + a2*a2;
    #pragma unroll
    for (int off = 16; off; off >>= 1) ss += __shfl_xor_sync(0xffffffffu, ss, off);
    if (lane == 0) g_rs[warp] = rsqrtf(ss * (1.0f/DM) + 1e-5f);
    atomicAdd(&su[lane],    a0);
    atomicAdd(&su[lane+32], a1);
    atomicAdd(&su[lane+64], a2);
    __syncthreads();
    if (tid < DM) atomicAdd(&g_usum[b*DM + tid], su[tid]);
}

// ---------------- kernel 2: tf32 tensor-core in-proj with fused rmsnorm ----------------
#define AST 52
#define BST 72
__device__ __forceinline__ void mma_tf32(float* c, const unsigned* a, unsigned b0, unsigned b1) {
    asm volatile(
        "mma.sync.aligned.m16n8k8.row.col.f32.tf32.tf32.f32 "
        "{%0,%1,%2,%3},{%4,%5,%6,%7},{%8,%9},{%0,%1,%2,%3};"
        : "+f"(c[0]), "+f"(c[1]), "+f"(c[2]), "+f"(c[3])
        : "r"(a[0]), "r"(a[1]), "r"(a[2]), "r"(a[3]), "r"(b0), "r"(b1));
}
__global__ __launch_bounds__(256) void k_inproj(const float* __restrict__ U,
                                                const float* __restrict__ W,
                                                const float* __restrict__ nw) {
    __shared__ float As[128*AST];
    __shared__ float Bs[48*BST];
    int m0 = blockIdx.x * 128;
    int n0 = blockIdx.y * 64;
    int tid = threadIdx.x;
    int w = tid >> 5, lane = tid & 31;
    int gi = lane >> 2, ti = lane & 3;
    float c[8][4];
    #pragma unroll
    for (int i = 0; i < 8; i++) { c[i][0]=0.f; c[i][1]=0.f; c[i][2]=0.f; c[i][3]=0.f; }

    for (int st = 0; st < 2; st++) {
        int kbase = st * 48;
        #pragma unroll
        for (int i = 0; i < 6; i++) {
            int e = tid + i*256;
            int r = e / 12, q = e % 12;
            float4 v = *(const float4*)&U[(size_t)(m0+r)*DM + kbase + 4*q];
            float* dst = &As[r*AST + 4*q];
            dst[0] = tf32r(v.x); dst[1] = tf32r(v.y); dst[2] = tf32r(v.z); dst[3] = tf32r(v.w);
        }
        #pragma unroll
        for (int i = 0; i < 3; i++) {
            int e = tid + i*256;
            int n = e / 12, q = e % 12;
            float4 v = *(const float4*)&W[(size_t)(n0+n)*DM + kbase + 4*q];
            float4 s = *(const float4*)&nw[kbase + 4*q];
            Bs[(4*q+0)*BST + n] = tf32r(v.x*s.x);
            Bs[(4*q+1)*BST + n] = tf32r(v.y*s.y);
            Bs[(4*q+2)*BST + n] = tf32r(v.z*s.z);
            Bs[(4*q+3)*BST + n] = tf32r(v.w*s.w);
        }
        __syncthreads();
        int ra = (w*16 + gi) * AST;
        #pragma unroll
        for (int kk = 0; kk < 6; kk++) {
            int k0 = kk * 8;
            unsigned a[4];
            a[0] = __float_as_uint(As[ra + k0 + ti]);
            a[1] = __float_as_uint(As[ra + 8*AST + k0 + ti]);
            a[2] = __float_as_uint(As[ra + k0 + ti + 4]);
            a[3] = __float_as_uint(As[ra + 8*AST + k0 + ti + 4]);
            #pragma unroll
            for (int nt = 0; nt < 8; nt++) {
                unsigned b0 = __float_as_uint(Bs[(k0+ti)*BST   + nt*8 + gi]);
                unsigned b1 = __float_as_uint(Bs[(k0+ti+4)*BST + nt*8 + gi]);
                mma_tf32(c[nt], a, b0, b1);
            }
        }
        __syncthreads();
    }
    int r0 = m0 + w*16 + gi;
    int r1 = r0 + 8;
    float rs0 = g_rs[r0], rs1 = g_rs[r1];
    bool zside = (n0 >= DI);
    #pragma unroll
    for (int nt = 0; nt < 8; nt++) {
        int n = n0 + nt*8 + 2*ti;
        float v00 = c[nt][0]*rs0, v01 = c[nt][1]*rs0;
        float v10 = c[nt][2]*rs1, v11 = c[nt][3]*rs1;
        if (!zside) {
            __nv_bfloat162 p0; p0.x = __float2bfloat16(v00); p0.y = __float2bfloat16(v01);
            __nv_bfloat162 p1; p1.x = __float2bfloat16(v10); p1.y = __float2bfloat16(v11);
            *(__nv_bfloat162*)&g_x[(size_t)r0*DI + n] = p0;
            *(__nv_bfloat162*)&g_x[(size_t)r1*DI + n] = p1;
        } else {
            int nz = n - DI;
            __nv_bfloat162 p0; p0.x = __float2bfloat16(siluf(v00)); p0.y = __float2bfloat16(siluf(v01));
            __nv_bfloat162 p1; p1.x = __float2bfloat16(siluf(v10)); p1.y = __float2bfloat16(siluf(v11));
            *(__nv_bfloat162*)&g_z[(size_t)r0*DI + nz] = p0;
            *(__nv_bfloat162*)&g_z[(size_t)r1*DI + nz] = p1;
        }
    }
}

// ---------------- kernel 3: conv + bf16-MMA dbc + delta + pack ----------------
// 32 tokens/block, 192 threads (6 warps). Thread tid owns channel d=tid.
#define XST 200   // bf16 row stride for sxc / sWb (conflict-free: banks 4*gi+ti)
__device__ __forceinline__ void mma_bf16(float* c, const unsigned* a, unsigned b0, unsigned b1) {
    asm volatile(
        "mma.sync.aligned.m16n8k16.row.col.f32.bf16.bf16.f32 "
        "{%0,%1,%2,%3},{%4,%5,%6,%7},{%8,%9},{%0,%1,%2,%3};"
        : "+f"(c[0]), "+f"(c[1]), "+f"(c[2]), "+f"(c[3])
        : "r"(a[0]), "r"(a[1]), "r"(a[2]), "r"(a[3]), "r"(b0), "r"(b1));
}
__global__ __launch_bounds__(192) void k_convdbc(
    const float* __restrict__ Wx, const float* __restrict__ Wdt,
    const float* __restrict__ bdt, const float* __restrict__ cw,
    const float* __restrict__ cb)
{
    __shared__ __nv_bfloat16 sxc[TCONV*XST];   // A: [t][k] bf16
    __shared__ __nv_bfloat16 sWb[24*XST];      // B: [j][k] bf16 (22 real + 2 zero)
    __shared__ float sdbc[TCONV*24];
    int tok0 = blockIdx.x * TCONV;
    int tid = threadIdx.x;
    int d = tid;  // 0..191

    #pragma unroll
    for (int j = 0; j < 22; j++) sWb[j*XST + tid] = __float2bfloat16(Wx[j*192 + tid]);
    sWb[22*XST + tid] = __float2bfloat16(0.0f);
    sWb[23*XST + tid] = __float2bfloat16(0.0f);

    // phase 1: causal depthwise conv + silu, rolling window
    {
        int t0 = tok0 & (LL - 1);
        float xm1, xm2;
        if (t0 == 0) { xm1 = 0.0f; xm2 = 0.0f; }
        else {
            xm1 = __bfloat162float(g_x[(size_t)(tok0-1)*DI + d]);
            xm2 = __bfloat162float(g_x[(size_t)(tok0-2)*DI + d]);
        }
        float w0 = cw[d*3+0], w1 = cw[d*3+1], w2 = cw[d*3+2], bb = cb[d];
        #pragma unroll 8
        for (int lt = 0; lt < TCONV; lt++) {
            float x0 = __bfloat162float(g_x[(size_t)(tok0+lt)*DI + d]);
            float v = w0*xm2 + w1*xm1 + w2*x0 + bb;
            sxc[lt*XST + d] = __float2bfloat16(siluf(v));
            xm2 = xm1; xm1 = x0;
        }
    }
    __syncthreads();

    // phase 2: dbc = xc @ Wx^T via bf16 mma m16n8k16. 6 warps: (mt 0..1) x (nt 0..2)
    {
        int w = tid >> 5, lane = tid & 31;
        int mt = w / 3, nt = w - mt*3;
        int gi = lane >> 2, ti = lane & 3;
        float c[4] = {0.f, 0.f, 0.f, 0.f};
        const __nv_bfloat16* ra  = &sxc[(mt*16 + gi)*XST];
        const __nv_bfloat16* ra8 = ra + 8*XST;
        const __nv_bfloat16* rb  = &sWb[(nt*8 + gi)*XST];
        #pragma unroll
        for (int kk = 0; kk < 12; kk++) {
            int k0 = kk*16 + 2*ti;
            unsigned a[4];
            a[0] = *(const unsigned*)&ra[k0];
            a[1] = *(const unsigned*)&ra8[k0];
            a[2] = *(const unsigned*)&ra[k0 + 8];
            a[3] = *(const unsigned*)&ra8[k0 + 8];
            unsigned b0 = *(const unsigned*)&rb[k0];
            unsigned b1 = *(const unsigned*)&rb[k0 + 8];
            mma_bf16(c, a, b0, b1);
        }
        int r0 = mt*16 + gi, n = nt*8 + 2*ti;
        sdbc[r0*24 + n]       = c[0];
        sdbc[r0*24 + n + 1]   = c[1];
        sdbc[(r0+8)*24 + n]     = c[2];
        sdbc[(r0+8)*24 + n + 1] = c[3];
    }
    __syncthreads();

    // phase 3a: delta = softplus(dt @ Wdt^T + bdt); pack {delta, xc} bf16
    {
        float wd0 = Wdt[d*DR+0], wd1 = Wdt[d*DR+1], wd2 = Wdt[d*DR+2];
        float wd3 = Wdt[d*DR+3], wd4 = Wdt[d*DR+4], wd5 = Wdt[d*DR+5];
        float bd = bdt[d];
        #pragma unroll 4
        for (int lt = 0; lt < TCONV; lt++) {
            const float* sb = &sdbc[lt*24];
            float dv = bd + sb[0]*wd0 + sb[1]*wd1 + sb[2]*wd2
                          + sb[3]*wd3 + sb[4]*wd4 + sb[5]*wd5;
            float delta = (dv > 20.0f) ? dv : __logf(1.0f + __expf(dv));
            __nv_bfloat162 p;
            p.x = __float2bfloat16(delta);
            p.y = sxc[lt*XST + d];
            g_dx[(size_t)(tok0+lt)*DI + d] = p;
        }
    }
    // phase 3b: extract B and C
    for (int e = tid; e < TCONV*16; e += 192) {
        int lt = e >> 4, j = e & 15;
        float v = sdbc[lt*24 + DR + j];
        size_t tok = (size_t)tok0 + lt;
        if (j < DS) g_Bm[tok*DS + j] = v;
        else        g_Cm[tok*DS + (j - DS)] = v;
    }
}

// ---------------- kernel 4: scan phase 1 (per-chunk local scan) ----------------
__global__ void k_scan1(const float* __restrict__ Alog) {
    int gid = blockIdx.x * blockDim.x + threadIdx.x;  // BB*NC*DI
    int d = gid % DI;
    int bc = gid / DI;
    int c = bc % NC;
    int b = bc / NC;
    float A0 = -__expf(Alog[d*DS]);
    float a0l = A0 * LOG2E;
    float ax[DS]; bool pw = true;
    #pragma unroll
    for (int s = 0; s < DS; s++) {
        float As = -__expf(Alog[d*DS+s]);
        ax[s] = As * LOG2E;
        pw = pw && (fabsf(As - (float)(s+1)*A0) <= 1e-4f * fabsf(As));
    }
    float h[DS];
    #pragma unroll
    for (int s = 0; s < DS; s++) h[s] = 0.0f;
    float S = 0.0f;
    size_t base = (size_t)b*LL + c*CS;
    if (pw) {
        #pragma unroll 2
        for (int t = 0; t < CS; t++) {
            size_t idx = base + t;
            __nv_bfloat162 p = g_dx[idx*DI + d];
            float delta = __bfloat162float(p.x);
            float x     = __bfloat162float(p.y);
            float4 B0 = *(const float4*)&g_Bm[idx*DS];
            float4 B1 = *(const float4*)&g_Bm[idx*DS + 4];
            S += delta;
            float E = ex2f(delta * a0l);
            float E2 = E*E, E4 = E2*E2, E8 = E4*E4;
            float E3 = E2*E, E5 = E4*E, E6 = E4*E2, E7 = E6*E;
            float dbx = delta * x;
            h[0] = E *h[0] + dbx*B0.x;
            h[1] = E2*h[1] + dbx*B0.y;
            h[2] = E3*h[2] + dbx*B0.z;
            h[3] = E4*h[3] + dbx*B0.w;
            h[4] = E5*h[4] + dbx*B1.x;
            h[5] = E6*h[5] + dbx*B1.y;
            h[6] = E7*h[6] + dbx*B1.z;
            h[7] = E8*h[7] + dbx*B1.w;
        }
    } else {
        for (int t = 0; t < CS; t++) {
            size_t idx = base + t;
            __nv_bfloat162 p = g_dx[idx*DI + d];
            float delta = __bfloat162float(p.x);
            float x     = __bfloat162float(p.y);
            float4 B0 = *(const float4*)&g_Bm[idx*DS];
            float4 B1 = *(const float4*)&g_Bm[idx*DS + 4];
            S += delta;
            float dbx = delta * x;
            h[0] = ex2f(delta*ax[0])*h[0] + dbx*B0.x;
            h[1] = ex2f(delta*ax[1])*h[1] + dbx*B0.y;
            h[2] = ex2f(delta*ax[2])*h[2] + dbx*B0.z;
            h[3] = ex2f(delta*ax[3])*h[3] + dbx*B0.w;
            h[4] = ex2f(delta*ax[4])*h[4] + dbx*B1.x;
            h[5] = ex2f(delta*ax[5])*h[5] + dbx*B1.y;
            h[6] = ex2f(delta*ax[6])*h[6] + dbx*B1.z;
            h[7] = ex2f(delta*ax[7])*h[7] + dbx*B1.w;
        }
    }
    size_t o = (size_t)(b*DI + d)*NC + c;
    g_S[o] = S;
    *(float4*)&g_hend[o*DS]     = make_float4(h[0], h[1], h[2], h[3]);
    *(float4*)&g_hend[o*DS + 4] = make_float4(h[4], h[5], h[6], h[7]);
}

// ---------------- kernel 5: sequential chunk combine ----------------
__global__ void k_comb(const float* __restrict__ Alog) {
    int gid = blockIdx.x * blockDim.x + threadIdx.x;  // BB*DI
    if (gid >= BB*DI) return;
    int d = gid % DI;
    float A0 = -__expf(Alog[d*DS]);
    float a0l = A0 * LOG2E;
    float ax[DS]; bool pw = true;
    #pragma unroll
    for (int s = 0; s < DS; s++) {
        float As = -__expf(Alog[d*DS+s]);
        ax[s] = As * LOG2E;
        pw = pw && (fabsf(As - (float)(s+1)*A0) <= 1e-4f * fabsf(As));
    }
    float h[DS];
    #pragma unroll
    for (int s = 0; s < DS; s++) h[s] = 0.0f;
    size_t o0 = (size_t)gid * NC;
    for (int c = 0; c < NC; c++) {
        size_t o = o0 + c;
        *(float4*)&g_hinit[o*DS]     = make_float4(h[0], h[1], h[2], h[3]);
        *(float4*)&g_hinit[o*DS + 4] = make_float4(h[4], h[5], h[6], h[7]);
        float S = g_S[o];
        float4 e0 = *(const float4*)&g_hend[o*DS];
        float4 e1 = *(const float4*)&g_hend[o*DS + 4];
        if (pw) {
            float E = ex2f(S * a0l);
            float E2 = E*E, E4 = E2*E2, E8 = E4*E4;
            float E3 = E2*E, E5 = E4*E, E6 = E4*E2, E7 = E6*E;
            h[0] = E *h[0] + e0.x;  h[1] = E2*h[1] + e0.y;
            h[2] = E3*h[2] + e0.z;  h[3] = E4*h[3] + e0.w;
            h[4] = E5*h[4] + e1.x;  h[5] = E6*h[5] + e1.y;
            h[6] = E7*h[6] + e1.z;  h[7] = E8*h[7] + e1.w;
        } else {
            h[0] = ex2f(S*ax[0])*h[0] + e0.x;  h[1] = ex2f(S*ax[1])*h[1] + e0.y;
            h[2] = ex2f(S*ax[2])*h[2] + e0.z;  h[3] = ex2f(S*ax[3])*h[3] + e0.w;
            h[4] = ex2f(S*ax[4])*h[4] + e1.x;  h[5] = ex2f(S*ax[5])*h[5] + e1.y;
            h[6] = ex2f(S*ax[6])*h[6] + e1.z;  h[7] = ex2f(S*ax[7])*h[7] + e1.w;
        }
    }
}

// ---------------- kernel 6: scan phase 3 (rescan + y accumulation) ----------------
__global__ void k_scan2(const float* __restrict__ Alog, const float* __restrict__ Dssm) {
    int gid = blockIdx.x * blockDim.x + threadIdx.x;
    int d = gid % DI;
    int bc = gid / DI;
    int c = bc % NC;
    int b = bc / NC;
    float A0 = -__expf(Alog[d*DS]);
    float a0l = A0 * LOG2E;
    float ax[DS]; bool pw = true;
    #pragma unroll
    for (int s = 0; s < DS; s++) {
        float As = -__expf(Alog[d*DS+s]);
        ax[s] = As * LOG2E;
        pw = pw && (fabsf(As - (float)(s+1)*A0) <= 1e-4f * fabsf(As));
    }
    float h[DS];
    size_t o = (size_t)(b*DI + d)*NC + c;
    {
        float4 h0 = *(const float4*)&g_hinit[o*DS];
        float4 h1 = *(const float4*)&g_hinit[o*DS + 4];
        h[0]=h0.x; h[1]=h0.y; h[2]=h0.z; h[3]=h0.w;
        h[4]=h1.x; h[5]=h1.y; h[6]=h1.z; h[7]=h1.w;
    }
    float Dd = Dssm[d];
    float acc = 0.0f;
    size_t base = (size_t)b*LL + c*CS;
    if (pw) {
        #pragma unroll 2
        for (int t = 0; t < CS; t++) {
            size_t idx = base + t;
            __nv_bfloat162 p = g_dx[idx*DI + d];
            float delta = __bfloat162float(p.x);
            float x     = __bfloat162float(p.y);
            float z     = __bfloat162float(g_z[idx*DI + d]);
            float4 B0 = *(const float4*)&g_Bm[idx*DS];
            float4 B1 = *(const float4*)&g_Bm[idx*DS + 4];
            float4 C0 = *(const float4*)&g_Cm[idx*DS];
            float4 C1 = *(const float4*)&g_Cm[idx*DS + 4];
            float E = ex2f(delta * a0l);
            float E2 = E*E, E4 = E2*E2, E8 = E4*E4;
            float E3 = E2*E, E5 = E4*E, E6 = E4*E2, E7 = E6*E;
            float dbx = delta * x;
            float y = Dd * x;
            h[0] = E *h[0] + dbx*B0.x;  y += h[0]*C0.x;
            h[1] = E2*h[1] + dbx*B0.y;  y += h[1]*C0.y;
            h[2] = E3*h[2] + dbx*B0.z;  y += h[2]*C0.z;
            h[3] = E4*h[3] + dbx*B0.w;  y += h[3]*C0.w;
            h[4] = E5*h[4] + dbx*B1.x;  y += h[4]*C1.x;
            h[5] = E6*h[5] + dbx*B1.y;  y += h[5]*C1.y;
            h[6] = E7*h[6] + dbx*B1.z;  y += h[6]*C1.z;
            h[7] = E8*h[7] + dbx*B1.w;  y += h[7]*C1.w;
            acc += y * z;
        }
    } else {
        for (int t = 0; t < CS; t++) {
            size_t idx = base + t;
            __nv_bfloat162 p = g_dx[idx*DI + d];
            float delta = __bfloat162float(p.x);
            float x     = __bfloat162float(p.y);
            float z     = __bfloat162float(g_z[idx*DI + d]);
            float4 B0 = *(const float4*)&g_Bm[idx*DS];
            float4 B1 = *(const float4*)&g_Bm[idx*DS + 4];
            float4 C0 = *(const float4*)&g_Cm[idx*DS];
            float4 C1 = *(const float4*)&g_Cm[idx*DS + 4];
            float dbx = delta * x;
            float y = Dd * x;
            h[0] = ex2f(delta*ax[0])*h[0] + dbx*B0.x;  y += h[0]*C0.x;
            h[1] = ex2f(delta*ax[1])*h[1] + dbx*B0.y;  y += h[1]*C0.y;
            h[2] = ex2f(delta*ax[2])*h[2] + dbx*B0.z;  y += h[2]*C0.z;
            h[3] = ex2f(delta*ax[3])*h[3] + dbx*B0.w;  y += h[3]*C0.w;
            h[4] = ex2f(delta*ax[4])*h[4] + dbx*B1.x;  y += h[4]*C1.x;
            h[5] = ex2f(delta*ax[5])*h[5] + dbx*B1.y;  y += h[5]*C1.y;
            h[6] = ex2f(delta*ax[6])*h[6] + dbx*B1.z;  y += h[6]*C1.z;
            h[7] = ex2f(delta*ax[7])*h[7] + dbx*B1.w;  y += h[7]*C1.w;
            acc += y * z;
        }
    }
    atomicAdd(&g_ysum[b*DI + d], acc);
}

// ---------------- kernel 7: out-proj of means + MLP heads ----------------
__global__ __launch_bounds__(256) void k_head(
    const float* __restrict__ Wout, const float* __restrict__ fw, const float* __restrict__ fb,
    const float* __restrict__ muw, const float* __restrict__ mub,
    const float* __restrict__ sw, const float* __restrict__ sb,
    float* __restrict__ out)
{
    int b = blockIdx.x;
    int tid = threadIdx.x;
    __shared__ float e[DM];
    __shared__ float h1[256];
    const float invL = 1.0f / LL;
    if (tid < DM) {
        float acc = g_usum[b*DM + tid] * invL;
        const float* wr = Wout + tid*DI;
        #pragma unroll 8
        for (int d = 0; d < DI; d++) acc += (g_ysum[b*DI + d] * invL) * wr[d];
        e[tid] = acc;
    }
    __syncthreads();
    {
        float v = fb[tid];
        const float* wr = fw + tid*DM;
        #pragma unroll 8
        for (int k = 0; k < DM; k++) v += e[k]*wr[k];
        float tv = tanhf(v);
        h1[tid] = (tv > 0.0f) ? tv : expm1f(tv);   // elu(tanh(v))
    }
    __syncthreads();
    if (tid < 64) {
        float m = mub[tid], s2 = sb[tid];
        const float* mr = muw + tid*256;
        const float* sr = sw + tid*256;
        #pragma unroll 8
        for (int i = 0; i < 256; i++) { m += h1[i]*mr[i]; s2 += h1[i]*sr[i]; }
        out[b*64 + tid] = m;                                     // mu
        float se = (s2 > 0.0f) ? s2 : expm1f(s2);                // elu
        out[512 + b*64 + tid] = se + 1.0f + 1e-14f;              // sigma
    }
}

// ---------------- launch ----------------
extern "C" void kernel_launch(void* const* d_in, const int* in_sizes, int n_in,
                              void* d_out, int out_size) {
    const float* input  = (const float*)d_in[0];
    const float* norm_w = (const float*)d_in[1];
    const float* W_in   = (const float*)d_in[2];
    const float* conv_w = (const float*)d_in[3];
    const float* conv_b = (const float*)d_in[4];
    const float* W_x    = (const float*)d_in[5];
    const float* W_dt   = (const float*)d_in[6];
    const float* b_dt   = (const float*)d_in[7];
    const float* A_log  = (const float*)d_in[8];
    const float* D_ssm  = (const float*)d_in[9];
    const float* W_out  = (const float*)d_in[10];
    const float* fc_w   = (const float*)d_in[11];
    const float* fc_b   = (const float*)d_in[12];
    const float* mu_w   = (const float*)d_in[13];
    const float* mu_b   = (const float*)d_in[14];
    const float* sg_w   = (const float*)d_in[15];
    const float* sg_b   = (const float*)d_in[16];
    float* out = (float*)d_out;

    k_zero<<<2, 1024>>>();
    k_rs<<<NTOK/8, 256>>>(input);
    {
        dim3 grid(NTOK/128, 384/64);
        k_inproj<<<grid, 256>>>(input, W_in, norm_w);
    }
    k_convdbc<<<NTOK/TCONV, 192>>>(W_x, W_dt, b_dt, conv_w, conv_b);
    k_scan1<<<(BB*NC*DI)/256, 256>>>(A_log);
    k_comb<<<6, 256>>>(A_log);
    k_scan2<<<(BB*NC*DI)/256, 256>>>(A_log, D_ssm);
    k_head<<<BB, 256>>>(W_out, fc_w, fc_b, mu_w, mu_b, sg_w, sg_b, out);
}

// round 10
// speedup vs baseline: 1.3219x; 1.3219x over previous
#include <cuda_runtime.h>
#include <cuda_bf16.h>
#include <math.h>
#include <stdint.h>

#define BB 8
#define LL 4096
#define DM 96
#define DI 192
#define DS 8
#define DR 6
#define NTOK (BB*LL)
#define CS 64
#define NC (LL/CS)
#define TCONV 32

// ---------------- scratch (device globals; no allocations) ----------------
__device__ float g_rs[NTOK];                 // per-token rsqrt(meansq+eps)
__device__ __nv_bfloat16 g_x[NTOK*DI];       // pre-conv x (bf16)
__device__ __nv_bfloat16 g_z[NTOK*DI];       // silu(z) (bf16)
__device__ __nv_bfloat162 g_dx[NTOK*DI];     // packed {delta, xc} bf16
__device__ float g_Bm[NTOK*DS];
__device__ float g_Cm[NTOK*DS];
__device__ float g_P[BB*DI*NC];              // per-chunk decay carrier (P if pw, else S)
__device__ float g_hend[BB*DI*NC*DS];        // per-chunk local h end
__device__ float g_G[BB*DI*NC*DS];           // per-chunk cross-term vector
__device__ float g_ysum[BB*DI];              // sum_t y_t*silu(z_t) per (b,d)
__device__ float g_usum[BB*DM];              // sum_t u per (b,k)

__device__ __forceinline__ float siluf(float v) { return v / (1.0f + __expf(-v)); }
__device__ __forceinline__ float ex2f(float x) { float y; asm("ex2.approx.f32 %0, %1;" : "=f"(y) : "f"(x)); return y; }
__device__ __forceinline__ float tf32r(float x) {
    unsigned u; asm("cvt.rna.tf32.f32 %0, %1;" : "=r"(u) : "f"(x)); return __uint_as_float(u);
}
#define LOG2E 1.4426950408889634f

// ---------------- kernel 0: zero accumulators ----------------
__global__ void k_zero() {
    int i = blockIdx.x * blockDim.x + threadIdx.x;
    if (i < BB*DM) g_usum[i] = 0.0f;
    if (i < BB*DI) g_ysum[i] = 0.0f;
}

// ---------------- kernel 1: per-row rsqrt + batch-mean (block-reduced) ----------------
__global__ void k_rs(const float* __restrict__ u) {
    __shared__ float su[DM];
    int tid = threadIdx.x;
    int warp = (blockIdx.x * blockDim.x + tid) >> 5;
    int lane = tid & 31;
    if (tid < DM) su[tid] = 0.0f;
    __syncthreads();
    int b = warp / LL;
    const float* up = u + (size_t)warp * DM;
    float a0 = up[lane], a1 = up[lane+32], a2 = up[lane+64];
    float ss = a0*a0 + a1*a1 + a2*a2;
    #pragma unroll
    for (int off = 16; off; off >>= 1) ss += __shfl_xor_sync(0xffffffffu, ss, off);
    if (lane == 0) g_rs[warp] = rsqrtf(ss * (1.0f/DM) + 1e-5f);
    atomicAdd(&su[lane],    a0);
    atomicAdd(&su[lane+32], a1);
    atomicAdd(&su[lane+64], a2);
    __syncthreads();
    if (tid < DM) atomicAdd(&g_usum[b*DM + tid], su[tid]);
}

// ---------------- kernel 2: tf32 tensor-core in-proj with fused rmsnorm ----------------
#define AST 52
#define BST 72
__device__ __forceinline__ void mma_tf32(float* c, const unsigned* a, unsigned b0, unsigned b1) {
    asm volatile(
        "mma.sync.aligned.m16n8k8.row.col.f32.tf32.tf32.f32 "
        "{%0,%1,%2,%3},{%4,%5,%6,%7},{%8,%9},{%0,%1,%2,%3};"
        : "+f"(c[0]), "+f"(c[1]), "+f"(c[2]), "+f"(c[3])
        : "r"(a[0]), "r"(a[1]), "r"(a[2]), "r"(a[3]), "r"(b0), "r"(b1));
}
__global__ __launch_bounds__(256) void k_inproj(const float* __restrict__ U,
                                                const float* __restrict__ W,
                                                const float* __restrict__ nw) {
    __shared__ float As[128*AST];
    __shared__ float Bs[48*BST];
    int m0 = blockIdx.x * 128;
    int n0 = blockIdx.y * 64;
    int tid = threadIdx.x;
    int w = tid >> 5, lane = tid & 31;
    int gi = lane >> 2, ti = lane & 3;
    float c[8][4];
    #pragma unroll
    for (int i = 0; i < 8; i++) { c[i][0]=0.f; c[i][1]=0.f; c[i][2]=0.f; c[i][3]=0.f; }

    for (int st = 0; st < 2; st++) {
        int kbase = st * 48;
        #pragma unroll
        for (int i = 0; i < 6; i++) {
            int e = tid + i*256;
            int r = e / 12, q = e % 12;
            float4 v = *(const float4*)&U[(size_t)(m0+r)*DM + kbase + 4*q];
            float* dst = &As[r*AST + 4*q];
            dst[0] = tf32r(v.x); dst[1] = tf32r(v.y); dst[2] = tf32r(v.z); dst[3] = tf32r(v.w);
        }
        #pragma unroll
        for (int i = 0; i < 3; i++) {
            int e = tid + i*256;
            int n = e / 12, q = e % 12;
            float4 v = *(const float4*)&W[(size_t)(n0+n)*DM + kbase + 4*q];
            float4 s = *(const float4*)&nw[kbase + 4*q];
            Bs[(4*q+0)*BST + n] = tf32r(v.x*s.x);
            Bs[(4*q+1)*BST + n] = tf32r(v.y*s.y);
            Bs[(4*q+2)*BST + n] = tf32r(v.z*s.z);
            Bs[(4*q+3)*BST + n] = tf32r(v.w*s.w);
        }
        __syncthreads();
        int ra = (w*16 + gi) * AST;
        #pragma unroll
        for (int kk = 0; kk < 6; kk++) {
            int k0 = kk * 8;
            unsigned a[4];
            a[0] = __float_as_uint(As[ra + k0 + ti]);
            a[1] = __float_as_uint(As[ra + 8*AST + k0 + ti]);
            a[2] = __float_as_uint(As[ra + k0 + ti + 4]);
            a[3] = __float_as_uint(As[ra + 8*AST + k0 + ti + 4]);
            #pragma unroll
            for (int nt = 0; nt < 8; nt++) {
                unsigned b0 = __float_as_uint(Bs[(k0+ti)*BST   + nt*8 + gi]);
                unsigned b1 = __float_as_uint(Bs[(k0+ti+4)*BST + nt*8 + gi]);
                mma_tf32(c[nt], a, b0, b1);
            }
        }
        __syncthreads();
    }
    int r0 = m0 + w*16 + gi;
    int r1 = r0 + 8;
    float rs0 = g_rs[r0], rs1 = g_rs[r1];
    bool zside = (n0 >= DI);
    #pragma unroll
    for (int nt = 0; nt < 8; nt++) {
        int n = n0 + nt*8 + 2*ti;
        float v00 = c[nt][0]*rs0, v01 = c[nt][1]*rs0;
        float v10 = c[nt][2]*rs1, v11 = c[nt][3]*rs1;
        if (!zside) {
            __nv_bfloat162 p0; p0.x = __float2bfloat16(v00); p0.y = __float2bfloat16(v01);
            __nv_bfloat162 p1; p1.x = __float2bfloat16(v10); p1.y = __float2bfloat16(v11);
            *(__nv_bfloat162*)&g_x[(size_t)r0*DI + n] = p0;
            *(__nv_bfloat162*)&g_x[(size_t)r1*DI + n] = p1;
        } else {
            int nz = n - DI;
            __nv_bfloat162 p0; p0.x = __float2bfloat16(siluf(v00)); p0.y = __float2bfloat16(siluf(v01));
            __nv_bfloat162 p1; p1.x = __float2bfloat16(siluf(v10)); p1.y = __float2bfloat16(siluf(v11));
            *(__nv_bfloat162*)&g_z[(size_t)r0*DI + nz] = p0;
            *(__nv_bfloat162*)&g_z[(size_t)r1*DI + nz] = p1;
        }
    }
}

// ---------------- kernel 3: conv + bf16-MMA dbc + delta + pack ----------------
#define XST 200
__device__ __forceinline__ void mma_bf16(float* c, const unsigned* a, unsigned b0, unsigned b1) {
    asm volatile(
        "mma.sync.aligned.m16n8k16.row.col.f32.bf16.bf16.f32 "
        "{%0,%1,%2,%3},{%4,%5,%6,%7},{%8,%9},{%0,%1,%2,%3};"
        : "+f"(c[0]), "+f"(c[1]), "+f"(c[2]), "+f"(c[3])
        : "r"(a[0]), "r"(a[1]), "r"(a[2]), "r"(a[3]), "r"(b0), "r"(b1));
}
__global__ __launch_bounds__(192) void k_convdbc(
    const float* __restrict__ Wx, const float* __restrict__ Wdt,
    const float* __restrict__ bdt, const float* __restrict__ cw,
    const float* __restrict__ cb)
{
    __shared__ __nv_bfloat16 sxc[TCONV*XST];
    __shared__ __nv_bfloat16 sWb[24*XST];
    __shared__ float sdbc[TCONV*24];
    int tok0 = blockIdx.x * TCONV;
    int tid = threadIdx.x;
    int d = tid;

    #pragma unroll
    for (int j = 0; j < 22; j++) sWb[j*XST + tid] = __float2bfloat16(Wx[j*192 + tid]);
    sWb[22*XST + tid] = __float2bfloat16(0.0f);
    sWb[23*XST + tid] = __float2bfloat16(0.0f);

    {
        int t0 = tok0 & (LL - 1);
        float xm1, xm2;
        if (t0 == 0) { xm1 = 0.0f; xm2 = 0.0f; }
        else {
            xm1 = __bfloat162float(g_x[(size_t)(tok0-1)*DI + d]);
            xm2 = __bfloat162float(g_x[(size_t)(tok0-2)*DI + d]);
        }
        float w0 = cw[d*3+0], w1 = cw[d*3+1], w2 = cw[d*3+2], bb = cb[d];
        #pragma unroll 8
        for (int lt = 0; lt < TCONV; lt++) {
            float x0 = __bfloat162float(g_x[(size_t)(tok0+lt)*DI + d]);
            float v = w0*xm2 + w1*xm1 + w2*x0 + bb;
            sxc[lt*XST + d] = __float2bfloat16(siluf(v));
            xm2 = xm1; xm1 = x0;
        }
    }
    __syncthreads();

    {
        int w = tid >> 5, lane = tid & 31;
        int mt = w / 3, nt = w - mt*3;
        int gi = lane >> 2, ti = lane & 3;
        float c[4] = {0.f, 0.f, 0.f, 0.f};
        const __nv_bfloat16* ra  = &sxc[(mt*16 + gi)*XST];
        const __nv_bfloat16* ra8 = ra + 8*XST;
        const __nv_bfloat16* rb  = &sWb[(nt*8 + gi)*XST];
        #pragma unroll
        for (int kk = 0; kk < 12; kk++) {
            int k0 = kk*16 + 2*ti;
            unsigned a[4];
            a[0] = *(const unsigned*)&ra[k0];
            a[1] = *(const unsigned*)&ra8[k0];
            a[2] = *(const unsigned*)&ra[k0 + 8];
            a[3] = *(const unsigned*)&ra8[k0 + 8];
            unsigned b0 = *(const unsigned*)&rb[k0];
            unsigned b1 = *(const unsigned*)&rb[k0 + 8];
            mma_bf16(c, a, b0, b1);
        }
        int r0 = mt*16 + gi, n = nt*8 + 2*ti;
        sdbc[r0*24 + n]       = c[0];
        sdbc[r0*24 + n + 1]   = c[1];
        sdbc[(r0+8)*24 + n]     = c[2];
        sdbc[(r0+8)*24 + n + 1] = c[3];
    }
    __syncthreads();

    {
        float wd0 = Wdt[d*DR+0], wd1 = Wdt[d*DR+1], wd2 = Wdt[d*DR+2];
        float wd3 = Wdt[d*DR+3], wd4 = Wdt[d*DR+4], wd5 = Wdt[d*DR+5];
        float bd = bdt[d];
        #pragma unroll 4
        for (int lt = 0; lt < TCONV; lt++) {
            const float* sb = &sdbc[lt*24];
            float dv = bd + sb[0]*wd0 + sb[1]*wd1 + sb[2]*wd2
                          + sb[3]*wd3 + sb[4]*wd4 + sb[5]*wd5;
            float delta = (dv > 20.0f) ? dv : __logf(1.0f + __expf(dv));
            __nv_bfloat162 p;
            p.x = __float2bfloat16(delta);
            p.y = sxc[lt*XST + d];
            g_dx[(size_t)(tok0+lt)*DI + d] = p;
        }
    }
    for (int e = tid; e < TCONV*16; e += 192) {
        int lt = e >> 4, j = e & 15;
        float v = sdbc[lt*24 + DR + j];
        size_t tok = (size_t)tok0 + lt;
        if (j < DS) g_Bm[tok*DS + j] = v;
        else        g_Cm[tok*DS + (j - DS)] = v;
    }
}

// ---------------- kernel 4: FUSED scan (single pass) ----------------
// Per (b, d, chunk): local scan h_local, accumulate acc = sum_t z_t*(C.h_local + D x),
// cross-term vector G_s = sum_t z_t C_ts decay_ts, chunk-end state hend, decay carrier.
__global__ void k_scan(const float* __restrict__ Alog, const float* __restrict__ Dssm) {
    int gid = blockIdx.x * blockDim.x + threadIdx.x;  // BB*NC*DI
    int d = gid % DI;
    int bc = gid / DI;
    int c = bc % NC;
    int b = bc / NC;
    float A0 = -__expf(Alog[d*DS]);
    float a0l = A0 * LOG2E;
    float ax[DS]; bool pw = true;
    #pragma unroll
    for (int s = 0; s < DS; s++) {
        float As = -__expf(Alog[d*DS+s]);
        ax[s] = As * LOG2E;
        pw = pw && (fabsf(As - (float)(s+1)*A0) <= 1e-4f * fabsf(As));
    }
    float h[DS], G[DS];
    #pragma unroll
    for (int s = 0; s < DS; s++) { h[s] = 0.0f; G[s] = 0.0f; }
    float Dd = Dssm[d];
    float acc = 0.0f;
    size_t base = (size_t)b*LL + c*CS;
    size_t o = (size_t)(b*DI + d)*NC + c;
    if (pw) {
        float P = 1.0f;
        #pragma unroll 2
        for (int t = 0; t < CS; t++) {
            size_t idx = base + t;
            __nv_bfloat162 p = g_dx[idx*DI + d];
            float delta = __bfloat162float(p.x);
            float x     = __bfloat162float(p.y);
            float z     = __bfloat162float(g_z[idx*DI + d]);
            float4 B0 = *(const float4*)&g_Bm[idx*DS];
            float4 B1 = *(const float4*)&g_Bm[idx*DS + 4];
            float4 C0 = *(const float4*)&g_Cm[idx*DS];
            float4 C1 = *(const float4*)&g_Cm[idx*DS + 4];
            float E = ex2f(delta * a0l);
            float E2 = E*E, E4 = E2*E2, E8 = E4*E4;
            float E3 = E2*E, E5 = E4*E, E6 = E4*E2, E7 = E6*E;
            float dbx = delta * x;
            float y = Dd * x;
            h[0] = E *h[0] + dbx*B0.x;  y += h[0]*C0.x;
            h[1] = E2*h[1] + dbx*B0.y;  y += h[1]*C0.y;
            h[2] = E3*h[2] + dbx*B0.z;  y += h[2]*C0.z;
            h[3] = E4*h[3] + dbx*B0.w;  y += h[3]*C0.w;
            h[4] = E5*h[4] + dbx*B1.x;  y += h[4]*C1.x;
            h[5] = E6*h[5] + dbx*B1.y;  y += h[5]*C1.y;
            h[6] = E7*h[6] + dbx*B1.z;  y += h[6]*C1.z;
            h[7] = E8*h[7] + dbx*B1.w;  y += h[7]*C1.w;
            acc += y * z;
            // cumulative decay (includes current step), cross-term accumulation
            P *= E;
            float zP = z * P;
            float P2 = P*P;
            float zP2 = z*P2, zP3 = zP2*P, zP4 = zP2*P2;
            float zP5 = zP4*P, zP6 = zP4*P2, zP7 = zP6*P, zP8 = zP6*P2;
            G[0] += C0.x*zP;   G[1] += C0.y*zP2;
            G[2] += C0.z*zP3;  G[3] += C0.w*zP4;
            G[4] += C1.x*zP5;  G[5] += C1.y*zP6;
            G[6] += C1.z*zP7;  G[7] += C1.w*zP8;
        }
        g_P[o] = P;
    } else {
        float Ps[DS];
        #pragma unroll
        for (int s = 0; s < DS; s++) Ps[s] = 1.0f;
        float S = 0.0f;
        for (int t = 0; t < CS; t++) {
            size_t idx = base + t;
            __nv_bfloat162 p = g_dx[idx*DI + d];
            float delta = __bfloat162float(p.x);
            float x     = __bfloat162float(p.y);
            float z     = __bfloat162float(g_z[idx*DI + d]);
            float4 B0 = *(const float4*)&g_Bm[idx*DS];
            float4 B1 = *(const float4*)&g_Bm[idx*DS + 4];
            float4 C0 = *(const float4*)&g_Cm[idx*DS];
            float4 C1 = *(const float4*)&g_Cm[idx*DS + 4];
            S += delta;
            float dbx = delta * x;
            float y = Dd * x;
            float Cv[DS] = {C0.x, C0.y, C0.z, C0.w, C1.x, C1.y, C1.z, C1.w};
            float Bv[DS] = {B0.x, B0.y, B0.z, B0.w, B1.x, B1.y, B1.z, B1.w};
            #pragma unroll
            for (int s = 0; s < DS; s++) {
                float E = ex2f(delta * ax[s]);
                h[s] = E*h[s] + dbx*Bv[s];
                y += h[s]*Cv[s];
                Ps[s] *= E;
                G[s] += z * Cv[s] * Ps[s];
            }
            acc += y * z;
        }
        g_P[o] = S;
    }
    atomicAdd(&g_ysum[b*DI + d], acc);
    *(float4*)&g_hend[o*DS]     = make_float4(h[0], h[1], h[2], h[3]);
    *(float4*)&g_hend[o*DS + 4] = make_float4(h[4], h[5], h[6], h[7]);
    *(float4*)&g_G[o*DS]        = make_float4(G[0], G[1], G[2], G[3]);
    *(float4*)&g_G[o*DS + 4]    = make_float4(G[4], G[5], G[6], G[7]);
}

// ---------------- kernel 5: sequential chunk combine + cross-term payout ----------------
__global__ void k_comb(const float* __restrict__ Alog) {
    int gid = blockIdx.x * blockDim.x + threadIdx.x;  // BB*DI
    if (gid >= BB*DI) return;
    int d = gid % DI;
    float A0 = -__expf(Alog[d*DS]);
    float ax[DS]; bool pw = true;
    #pragma unroll
    for (int s = 0; s < DS; s++) {
        float As = -__expf(Alog[d*DS+s]);
        ax[s] = As * LOG2E;
        pw = pw && (fabsf(As - (float)(s+1)*A0) <= 1e-4f * fabsf(As));
    }
    float h[DS];
    #pragma unroll
    for (int s = 0; s < DS; s++) h[s] = 0.0f;
    float ytot = 0.0f;
    size_t o0 = (size_t)gid * NC;
    for (int c = 0; c < NC; c++) {
        size_t o = o0 + c;
        float Pe = g_P[o];
        float4 e0 = *(const float4*)&g_hend[o*DS];
        float4 e1 = *(const float4*)&g_hend[o*DS + 4];
        float4 g0 = *(const float4*)&g_G[o*DS];
        float4 g1 = *(const float4*)&g_G[o*DS + 4];
        // cross term: hinit (current h) dotted with G
        ytot += h[0]*g0.x + h[1]*g0.y + h[2]*g0.z + h[3]*g0.w
              + h[4]*g1.x + h[5]*g1.y + h[6]*g1.z + h[7]*g1.w;
        if (pw) {
            float P = Pe;
            float P2 = P*P, P4 = P2*P2, P8 = P4*P4;
            float P3 = P2*P, P5 = P4*P, P6 = P4*P2, P7 = P6*P;
            h[0] = P *h[0] + e0.x;  h[1] = P2*h[1] + e0.y;
            h[2] = P3*h[2] + e0.z;  h[3] = P4*h[3] + e0.w;
            h[4] = P5*h[4] + e1.x;  h[5] = P6*h[5] + e1.y;
            h[6] = P7*h[6] + e1.z;  h[7] = P8*h[7] + e1.w;
        } else {
            float S = Pe;
            h[0] = ex2f(S*ax[0])*h[0] + e0.x;  h[1] = ex2f(S*ax[1])*h[1] + e0.y;
            h[2] = ex2f(S*ax[2])*h[2] + e0.z;  h[3] = ex2f(S*ax[3])*h[3] + e0.w;
            h[4] = ex2f(S*ax[4])*h[4] + e1.x;  h[5] = ex2f(S*ax[5])*h[5] + e1.y;
            h[6] = ex2f(S*ax[6])*h[6] + e1.z;  h[7] = ex2f(S*ax[7])*h[7] + e1.w;
        }
    }
    g_ysum[gid] += ytot;
}

// ---------------- kernel 7: out-proj of means + MLP heads ----------------
__global__ __launch_bounds__(256) void k_head(
    const float* __restrict__ Wout, const float* __restrict__ fw, const float* __restrict__ fb,
    const float* __restrict__ muw, const float* __restrict__ mub,
    const float* __restrict__ sw, const float* __restrict__ sb,
    float* __restrict__ out)
{
    int b = blockIdx.x;
    int tid = threadIdx.x;
    __shared__ float e[DM];
    __shared__ float h1[256];
    const float invL = 1.0f / LL;
    if (tid < DM) {
        float acc = g_usum[b*DM + tid] * invL;
        const float* wr = Wout + tid*DI;
        #pragma unroll 8
        for (int d = 0; d < DI; d++) acc += (g_ysum[b*DI + d] * invL) * wr[d];
        e[tid] = acc;
    }
    __syncthreads();
    {
        float v = fb[tid];
        const float* wr = fw + tid*DM;
        #pragma unroll 8
        for (int k = 0; k < DM; k++) v += e[k]*wr[k];
        float tv = tanhf(v);
        h1[tid] = (tv > 0.0f) ? tv : expm1f(tv);   // elu(tanh(v))
    }
    __syncthreads();
    if (tid < 64) {
        float m = mub[tid], s2 = sb[tid];
        const float* mr = muw + tid*256;
        const float* sr = sw + tid*256;
        #pragma unroll 8
        for (int i = 0; i < 256; i++) { m += h1[i]*mr[i]; s2 += h1[i]*sr[i]; }
        out[b*64 + tid] = m;                                     // mu
        float se = (s2 > 0.0f) ? s2 : expm1f(s2);                // elu
        out[512 + b*64 + tid] = se + 1.0f + 1e-14f;              // sigma
    }
}

// ---------------- launch ----------------
extern "C" void kernel_launch(void* const* d_in, const int* in_sizes, int n_in,
                              void* d_out, int out_size) {
    const float* input  = (const float*)d_in[0];
    const float* norm_w = (const float*)d_in[1];
    const float* W_in   = (const float*)d_in[2];
    const float* conv_w = (const float*)d_in[3];
    const float* conv_b = (const float*)d_in[4];
    const float* W_x    = (const float*)d_in[5];
    const float* W_dt   = (const float*)d_in[6];
    const float* b_dt   = (const float*)d_in[7];
    const float* A_log  = (const float*)d_in[8];
    const float* D_ssm  = (const float*)d_in[9];
    const float* W_out  = (const float*)d_in[10];
    const float* fc_w   = (const float*)d_in[11];
    const float* fc_b   = (const float*)d_in[12];
    const float* mu_w   = (const float*)d_in[13];
    const float* mu_b   = (const float*)d_in[14];
    const float* sg_w   = (const float*)d_in[15];
    const float* sg_b   = (const float*)d_in[16];
    float* out = (float*)d_out;

    k_zero<<<2, 1024>>>();
    k_rs<<<NTOK/8, 256>>>(input);
    {
        dim3 grid(NTOK/128, 384/64);
        k_inproj<<<grid, 256>>>(input, W_in, norm_w);
    }
    k_convdbc<<<NTOK/TCONV, 192>>>(W_x, W_dt, b_dt, conv_w, conv_b);
    k_scan<<<(BB*NC*DI)/256, 256>>>(A_log, D_ssm);
    k_comb<<<6, 256>>>(A_log);
    k_head<<<BB, 256>>>(W_out, fc_w, fc_b, mu_w, mu_b, sg_w, sg_b, out);
}